// round 12
// baseline (speedup 1.0000x reference)
#include <cuda_runtime.h>
#include <cstdint>
typedef unsigned long long ull;

#define B_ 32
#define T_ 2048
#define D_ 256
#define H_ 512
#define O_ 256
#define BT_ 65536
#define CH_ 32
#define NCH_ 64

__device__ __align__(16) float g_xw[(size_t)BT_ * H_];
__device__ __align__(16) float g_Sa[NCH_ * B_ * H_];
__device__ __align__(16) float g_Sb[NCH_ * B_ * H_];
__device__ __align__(16) float g_Hinit[(NCH_ + 1) * B_ * H_];
__device__ __align__(16) float g_p0[H_ * H_];
__device__ __align__(16) float g_p1[H_ * H_];
__device__ volatile unsigned g_flags[128];
__device__ volatile unsigned g_rel;

#define FMA2(d,a,b) asm("fma.rn.f32x2 %0, %1, %2, %0;" : "+l"(d) : "l"(a), "l"(b))
#define PACK2(o,x) { unsigned u_ = __float_as_uint(x); \
    asm("mov.b64 %0,{%1,%1};" : "=l"(o) : "r"(u_)); }

// mode 0: linear rows (r*ld). mode 1: (b,t)-mapped rows of a [B][T][H] tensor,
// r -> b = r&31, chunk = r>>5, t = chunk*CH_ + i.
__device__ __forceinline__ size_t rowoff(int mode, long r, int i, int ld) {
    if (mode == 0) return (size_t)r * ld;
    return ((size_t)(r & 31) * T_ + (size_t)(r >> 5) * CH_ + i) * H_;
}

// ============================================================================
// Unified NT GEMM, tile 128(M)x64(N)x16(K), 256 threads, micro 8mx4n, FFMA2.
// C[m][n] = sum_k A[m][k]*Bm[n][k] (+ Add[m][n]) (+ bias1[n] (+ bias2[n]))
// ============================================================================
__global__ __launch_bounds__(256) void gemm_u(
    const float* __restrict__ A, int aMode, int ai, int lda,
    const float* __restrict__ Bm, int K,
    float* __restrict__ C, int cMode, int ci, int ldc,
    const float* __restrict__ Add, int addi,
    const float* __restrict__ bias1, const float* __restrict__ bias2)
{
    __shared__ float As[16][132];
    __shared__ float Bs[16][68];
    const int tid = threadIdx.x;
    const long m0 = (long)blockIdx.y * 128;
    const int n0 = blockIdx.x * 64;
    const int ty = tid >> 4, tx = tid & 15;
    const int ar = tid >> 1, ak = (tid & 1) * 8;
    const int br = tid >> 2, bk = (tid & 3) * 4;
    const float* Ap = A + rowoff(aMode, m0 + ar, ai, lda) + ak;
    const float* Bp = Bm + (size_t)(n0 + br) * K + bk;

    ull acc[4][4] = {};
    for (int k0 = 0; k0 < K; k0 += 16) {
        float4 a0 = *(const float4*)(Ap + k0);
        float4 a1 = *(const float4*)(Ap + k0 + 4);
        float4 bv = *(const float4*)(Bp + k0);
        __syncthreads();
        As[ak + 0][ar] = a0.x; As[ak + 1][ar] = a0.y;
        As[ak + 2][ar] = a0.z; As[ak + 3][ar] = a0.w;
        As[ak + 4][ar] = a1.x; As[ak + 5][ar] = a1.y;
        As[ak + 6][ar] = a1.z; As[ak + 7][ar] = a1.w;
        Bs[bk + 0][br] = bv.x; Bs[bk + 1][br] = bv.y;
        Bs[bk + 2][br] = bv.z; Bs[bk + 3][br] = bv.w;
        __syncthreads();
#pragma unroll
        for (int k = 0; k < 16; k++) {
            const ull* ap = (const ull*)&As[k][ty * 8];
            ull a2[4] = { ap[0], ap[1], ap[2], ap[3] };
            float4 b = *(const float4*)&Bs[k][tx * 4];
            ull b2[4];
            PACK2(b2[0], b.x); PACK2(b2[1], b.y);
            PACK2(b2[2], b.z); PACK2(b2[3], b.w);
#pragma unroll
            for (int p = 0; p < 4; p++)
#pragma unroll
                for (int j = 0; j < 4; j++) FMA2(acc[p][j], a2[p], b2[j]);
        }
    }

    float bs[4] = {0.f, 0.f, 0.f, 0.f};
    if (bias1) {
#pragma unroll
        for (int j = 0; j < 4; j++) bs[j] = bias1[n0 + tx * 4 + j];
    }
    if (bias2) {
#pragma unroll
        for (int j = 0; j < 4; j++) bs[j] += bias2[n0 + tx * 4 + j];
    }
#pragma unroll
    for (int p = 0; p < 4; p++) {
#pragma unroll
        for (int h = 0; h < 2; h++) {
            long m = m0 + ty * 8 + p * 2 + h;
            float4 v;
            v.x = __uint_as_float((unsigned)(acc[p][0] >> (h * 32))) + bs[0];
            v.y = __uint_as_float((unsigned)(acc[p][1] >> (h * 32))) + bs[1];
            v.z = __uint_as_float((unsigned)(acc[p][2] >> (h * 32))) + bs[2];
            v.w = __uint_as_float((unsigned)(acc[p][3] >> (h * 32))) + bs[3];
            if (Add) {
                float4 ad = *(const float4*)(Add + rowoff(1, m, addi, H_) + n0 + tx * 4);
                v.x += ad.x; v.y += ad.y; v.z += ad.z; v.w += ad.w;
            }
            *(float4*)(C + rowoff(cMode, m, ci, ldc) + n0 + tx * 4) = v;
        }
    }
}

// ============================================================================
// NN GEMM for matrix powers: C = A @ B, 512x512x512 row-major.
// Grid 128 (16mt x 8nt), tile 32m x 64n, K-tile 16, 256 threads, 2x4 micro.
// ============================================================================
__global__ __launch_bounds__(256) void gemm_nn_pow(
    const float* __restrict__ A, const float* __restrict__ Bm, float* __restrict__ C)
{
    __shared__ float As[16 * 36];
    __shared__ float Bs[16 * 68];
    const int tid = threadIdx.x;
    const int mt = blockIdx.x >> 3, nt = blockIdx.x & 7;
    const int ty = tid >> 4, tx = tid & 15;
    float acc[2][4] = {};
    for (int k0 = 0; k0 < H_; k0 += 16) {
        __syncthreads();
        if (tid < 128) {
            int m = tid >> 2, k4 = (tid & 3) * 4;
            float4 a = *(const float4*)(A + (size_t)(mt * 32 + m) * H_ + k0 + k4);
            As[(k4 + 0) * 36 + m] = a.x; As[(k4 + 1) * 36 + m] = a.y;
            As[(k4 + 2) * 36 + m] = a.z; As[(k4 + 3) * 36 + m] = a.w;
        }
        {
            int k = tid >> 4, j4 = (tid & 15) * 4;
            float4 b = *(const float4*)(Bm + (size_t)(k0 + k) * H_ + nt * 64 + j4);
            *(float4*)(Bs + k * 68 + j4) = b;
        }
        __syncthreads();
#pragma unroll
        for (int kk = 0; kk < 16; kk++) {
            float a0 = As[kk * 36 + ty * 2];
            float a1 = As[kk * 36 + ty * 2 + 1];
            float4 b = *(const float4*)(Bs + kk * 68 + tx * 4);
            acc[0][0] = fmaf(a0, b.x, acc[0][0]); acc[0][1] = fmaf(a0, b.y, acc[0][1]);
            acc[0][2] = fmaf(a0, b.z, acc[0][2]); acc[0][3] = fmaf(a0, b.w, acc[0][3]);
            acc[1][0] = fmaf(a1, b.x, acc[1][0]); acc[1][1] = fmaf(a1, b.y, acc[1][1]);
            acc[1][2] = fmaf(a1, b.z, acc[1][2]); acc[1][3] = fmaf(a1, b.w, acc[1][3]);
        }
    }
#pragma unroll
    for (int im = 0; im < 2; im++) {
        float4 o = { acc[im][0], acc[im][1], acc[im][2], acc[im][3] };
        *(float4*)(C + (size_t)(mt * 32 + ty * 2 + im) * H_ + nt * 64 + tx * 4) = o;
    }
}

// ============================================================================
// Phase B: persistent 64-step boundary scan. Hn[t+1] = Hn[t] @ Q^T + F[t].
// 128 CTAs x 128 thr; CTA c: bg=c&3 (8 b's), jg=c>>2 (16 j's). Q in smem.
// Monotonic replay-safe grid barrier (R2-proven).
// ============================================================================
__global__ __launch_bounds__(128) void phaseB(
    const float* __restrict__ F, const float* __restrict__ Q, float* __restrict__ Hn)
{
    extern __shared__ float sm[];
    float (*Wsm)[516] = (float(*)[516])sm;
    float (*hsm)[516] = (float(*)[516])(sm + 16 * 516);
    float (*red)[132] = (float(*)[132])(sm + 24 * 516);
    const int tid = threadIdx.x, c = blockIdx.x, bg = c & 3, jg = c >> 2;

    for (int i = tid; i < 16 * 128; i += 128) {
        int row = i >> 7, c4 = (i & 127) << 2;
        *(float4*)&Wsm[row][c4] = *(const float4*)(Q + (size_t)(jg * 16 + row) * H_ + c4);
    }
    const unsigned base = g_flags[c];
    const int ks = tid >> 3, pos = tid & 7;
    const int pb = (pos & 1) * 4, pj = (pos >> 1) * 4, kc = ks * 4;

    for (int t = 0; t < NCH_; t++) {
        for (int i = tid; i < 1024; i += 128) {
            int rb = i >> 7, c4 = (i & 127) << 2;
            *(float4*)&hsm[rb][c4] =
                __ldcg((const float4*)(Hn + ((size_t)t * B_ + bg * 8 + rb) * H_ + c4));
        }
        __syncthreads();
        float acc[4][4] = {};
#pragma unroll
        for (int g = 0; g < 8; g++) {
            int col = g * 64 + kc;
            float4 h4[4], w4[4];
#pragma unroll
            for (int i = 0; i < 4; i++) h4[i] = *(const float4*)&hsm[pb + i][col];
#pragma unroll
            for (int j = 0; j < 4; j++) w4[j] = *(const float4*)&Wsm[pj + j][col];
#pragma unroll
            for (int i = 0; i < 4; i++)
#pragma unroll
                for (int j = 0; j < 4; j++) {
                    acc[i][j] = fmaf(h4[i].x, w4[j].x, acc[i][j]);
                    acc[i][j] = fmaf(h4[i].y, w4[j].y, acc[i][j]);
                    acc[i][j] = fmaf(h4[i].z, w4[j].z, acc[i][j]);
                    acc[i][j] = fmaf(h4[i].w, w4[j].w, acc[i][j]);
                }
        }
#pragma unroll
        for (int i = 0; i < 4; i++)
#pragma unroll
            for (int j = 0; j < 4; j++)
                red[ks][(pb + i) * 16 + pj + j] = acc[i][j];
        __syncthreads();
        float s = 0.f;
#pragma unroll
        for (int q = 0; q < 16; q++) s += red[q][tid];

        const int bl = tid >> 4, jl = tid & 15;
        const int b = bg * 8 + bl, j = jg * 16 + jl;
        Hn[((size_t)(t + 1) * B_ + b) * H_ + j] = s + F[((size_t)t * B_ + b) * H_ + j];

        __threadfence();
        __syncthreads();
        const unsigned tgt = base + (unsigned)t + 1u;
        if (tid == 0) g_flags[c] = tgt;
        if (c == 0 && tid < 32) {
            for (;;) {
                bool ok = true;
                for (int q = tid; q < 128; q += 32)
                    if ((int)(g_flags[q] - tgt) < 0) ok = false;
                if (__all_sync(0xffffffffu, ok)) break;
            }
            if (tid == 0) { __threadfence(); g_rel = tgt; }
        }
        if (tid == 0) { while ((int)(g_rel - tgt) < 0) {} }
        __syncthreads();
        __threadfence();
    }
}

// ============================================================================
// Row softmax over 256 cols, one warp per row, in place.
// ============================================================================
__global__ __launch_bounds__(256) void softmax_rows(float* __restrict__ C)
{
    const int row = blockIdx.x * 8 + (threadIdx.x >> 5);
    const int lane = threadIdx.x & 31;
    float* p = C + (size_t)row * O_;
    float4 v0 = *(const float4*)(p + lane * 8);
    float4 v1 = *(const float4*)(p + lane * 8 + 4);
    float mx = fmaxf(fmaxf(fmaxf(v0.x, v0.y), fmaxf(v0.z, v0.w)),
                     fmaxf(fmaxf(v1.x, v1.y), fmaxf(v1.z, v1.w)));
#pragma unroll
    for (int o = 16; o; o >>= 1) mx = fmaxf(mx, __shfl_xor_sync(0xffffffffu, mx, o));
    v0.x = __expf(v0.x - mx); v0.y = __expf(v0.y - mx);
    v0.z = __expf(v0.z - mx); v0.w = __expf(v0.w - mx);
    v1.x = __expf(v1.x - mx); v1.y = __expf(v1.y - mx);
    v1.z = __expf(v1.z - mx); v1.w = __expf(v1.w - mx);
    float s = v0.x + v0.y + v0.z + v0.w + v1.x + v1.y + v1.z + v1.w;
#pragma unroll
    for (int o = 16; o; o >>= 1) s += __shfl_xor_sync(0xffffffffu, s, o);
    const float inv = 1.0f / s;
    v0.x *= inv; v0.y *= inv; v0.z *= inv; v0.w *= inv;
    v1.x *= inv; v1.y *= inv; v1.z *= inv; v1.w *= inv;
    *(float4*)(p + lane * 8) = v0;
    *(float4*)(p + lane * 8 + 4) = v1;
}

// ============================================================================
// Orchestration. Output layout: [ out (B,T,O) | z (B,T,H) ]
// ============================================================================
extern "C" void kernel_launch(void* const* d_in, const int* in_sizes, int n_in,
                              void* d_out, int out_size)
{
    (void)in_sizes; (void)n_in; (void)out_size;
    const float* x     = (const float*)d_in[0];
    const float* h0    = (const float*)d_in[1];
    const float* W_ih  = (const float*)d_in[2];
    const float* W_hh  = (const float*)d_in[3];
    const float* b_ih  = (const float*)d_in[4];
    const float* b_hh  = (const float*)d_in[5];
    const float* W_lin = (const float*)d_in[6];
    const float* b_lin = (const float*)d_in[7];

    float* outp = (float*)d_out;
    float* zp = outp + (size_t)B_ * T_ * O_;

    float *xw, *Sa, *Sb, *Hin, *p0, *p1;
    cudaGetSymbolAddress((void**)&xw, g_xw);
    cudaGetSymbolAddress((void**)&Sa, g_Sa);
    cudaGetSymbolAddress((void**)&Sb, g_Sb);
    cudaGetSymbolAddress((void**)&Hin, g_Hinit);
    cudaGetSymbolAddress((void**)&p0, g_p0);
    cudaGetSymbolAddress((void**)&p1, g_p1);

    const int pb_smem = (24 * 516 + 16 * 132) * 4;
    cudaFuncSetAttribute(phaseB, cudaFuncAttributeMaxDynamicSharedMemorySize, pb_smem);

    // Q = W_hh^32 via 5 squarings (so (W^T)^32 = Q^T, NT-compatible)
    gemm_nn_pow<<<128, 256>>>(W_hh, W_hh, p0);
    gemm_nn_pow<<<128, 256>>>(p0, p0, p1);
    gemm_nn_pow<<<128, 256>>>(p1, p1, p0);
    gemm_nn_pow<<<128, 256>>>(p0, p0, p1);
    gemm_nn_pow<<<128, 256>>>(p1, p1, p0);

    // H_init[0] = h0
    cudaMemcpyAsync(Hin, h0, (size_t)B_ * H_ * sizeof(float),
                    cudaMemcpyDeviceToDevice, 0);

    // xw = x @ W_ih^T + (b_ih + b_hh)   [65536 x 512], K=256
    gemm_u<<<dim3(8, 512), 256>>>(x, 0, 0, D_, W_ih, D_,
                                  xw, 0, 0, H_, nullptr, 0, b_ih, b_hh);

    // Phase A: chunks from zero init; S_i = S_{i-1} @ W^T + xw_i. F -> g_Sa.
    gemm_u<<<dim3(8, 16), 256>>>(xw, 1, 0, H_, W_hh, H_,
                                 Sa, 0, 0, H_, xw, 1, nullptr, nullptr);
    for (int i = 2; i < CH_; i++) {
        const float* src = (i & 1) ? Sb : Sa;
        float* dst = (i & 1) ? Sa : Sb;
        gemm_u<<<dim3(8, 16), 256>>>(src, 0, 0, H_, W_hh, H_,
                                     dst, 0, 0, H_, xw, i, nullptr, nullptr);
    }

    // Phase B: 64 sequential boundary combines
    phaseB<<<128, 128, pb_smem>>>(Sa, p0, Hin);

    // Phase C: re-run chunks from true boundary states, write z
    gemm_u<<<dim3(8, 16), 256>>>(Hin, 0, 0, H_, W_hh, H_,
                                 zp, 1, 0, H_, xw, 0, nullptr, nullptr);
    for (int i = 1; i < CH_; i++)
        gemm_u<<<dim3(8, 16), 256>>>(zp, 1, i - 1, H_, W_hh, H_,
                                     zp, 1, i, H_, xw, i, nullptr, nullptr);

    // logits = z @ W_lin^T + b_lin   [65536 x 256], K=512
    gemm_u<<<dim3(4, 512), 256>>>(zp, 0, 0, H_, W_lin, H_,
                                  outp, 0, 0, O_, nullptr, 0, b_lin, nullptr);

    softmax_rows<<<BT_ / 8, 256>>>(outp);
}

// round 13
// speedup vs baseline: 1.0067x; 1.0067x over previous
#include <cuda_runtime.h>
#include <cstdint>
typedef unsigned long long ull;

#define B_ 32
#define T_ 2048
#define D_ 256
#define H_ 512
#define O_ 256
#define BT_ 65536
#define CH_ 32
#define NCH_ 64

__device__ __align__(16) float g_xw[(size_t)BT_ * H_];
__device__ __align__(16) float g_Sa[NCH_ * B_ * H_];
__device__ __align__(16) float g_Sb[NCH_ * B_ * H_];
__device__ __align__(16) float g_Hinit[(NCH_ + 1) * B_ * H_];
__device__ __align__(16) float g_p0[H_ * H_];
__device__ __align__(16) float g_p1[H_ * H_];
__device__ volatile unsigned g_flags[128];
__device__ volatile unsigned g_rel;

#define FMA2(d,a,b) asm("fma.rn.f32x2 %0, %1, %2, %0;" : "+l"(d) : "l"(a), "l"(b))
#define PACK2(o,x) { unsigned u_ = __float_as_uint(x); \
    asm("mov.b64 %0,{%1,%1};" : "=l"(o) : "r"(u_)); }

// mode 0: linear rows (r*ld). mode 1: (b,t)-mapped rows of a [B][T][H] tensor,
// r -> b = r&31, chunk = r>>5, t = chunk*CH_ + i.
__device__ __forceinline__ size_t rowoff(int mode, long r, int i, int ld) {
    if (mode == 0) return (size_t)r * ld;
    return ((size_t)(r & 31) * T_ + (size_t)(r >> 5) * CH_ + i) * H_;
}

// ============================================================================
// Unified NT GEMM, tile 128(M)x64(N)x16(K), 256 threads, micro 8mx4n, FFMA2.
// C[m][n] = sum_k A[m][k]*Bm[n][k] (+ Add[m][n]) (+ bias1[n] (+ bias2[n]))
// ============================================================================
__global__ __launch_bounds__(256) void gemm_u(
    const float* __restrict__ A, int aMode, int ai, int lda,
    const float* __restrict__ Bm, int K,
    float* __restrict__ C, int cMode, int ci, int ldc,
    const float* __restrict__ Add, int addi,
    const float* __restrict__ bias1, const float* __restrict__ bias2)
{
    __shared__ float As[16][132];
    __shared__ float Bs[16][68];
    const int tid = threadIdx.x;
    const long m0 = (long)blockIdx.y * 128;
    const int n0 = blockIdx.x * 64;
    const int ty = tid >> 4, tx = tid & 15;
    const int ar = tid >> 1, ak = (tid & 1) * 8;
    const int br = tid >> 2, bk = (tid & 3) * 4;
    const float* Ap = A + rowoff(aMode, m0 + ar, ai, lda) + ak;
    const float* Bp = Bm + (size_t)(n0 + br) * K + bk;

    ull acc[4][4] = {};
    for (int k0 = 0; k0 < K; k0 += 16) {
        float4 a0 = *(const float4*)(Ap + k0);
        float4 a1 = *(const float4*)(Ap + k0 + 4);
        float4 bv = *(const float4*)(Bp + k0);
        __syncthreads();
        As[ak + 0][ar] = a0.x; As[ak + 1][ar] = a0.y;
        As[ak + 2][ar] = a0.z; As[ak + 3][ar] = a0.w;
        As[ak + 4][ar] = a1.x; As[ak + 5][ar] = a1.y;
        As[ak + 6][ar] = a1.z; As[ak + 7][ar] = a1.w;
        Bs[bk + 0][br] = bv.x; Bs[bk + 1][br] = bv.y;
        Bs[bk + 2][br] = bv.z; Bs[bk + 3][br] = bv.w;
        __syncthreads();
#pragma unroll
        for (int k = 0; k < 16; k++) {
            const ull* ap = (const ull*)&As[k][ty * 8];
            ull a2[4] = { ap[0], ap[1], ap[2], ap[3] };
            float4 b = *(const float4*)&Bs[k][tx * 4];
            ull b2[4];
            PACK2(b2[0], b.x); PACK2(b2[1], b.y);
            PACK2(b2[2], b.z); PACK2(b2[3], b.w);
#pragma unroll
            for (int p = 0; p < 4; p++)
#pragma unroll
                for (int j = 0; j < 4; j++) FMA2(acc[p][j], a2[p], b2[j]);
        }
    }

    float bs[4] = {0.f, 0.f, 0.f, 0.f};
    if (bias1) {
#pragma unroll
        for (int j = 0; j < 4; j++) bs[j] = bias1[n0 + tx * 4 + j];
    }
    if (bias2) {
#pragma unroll
        for (int j = 0; j < 4; j++) bs[j] += bias2[n0 + tx * 4 + j];
    }
#pragma unroll
    for (int p = 0; p < 4; p++) {
#pragma unroll
        for (int h = 0; h < 2; h++) {
            long m = m0 + ty * 8 + p * 2 + h;
            float4 v;
            v.x = __uint_as_float((unsigned)(acc[p][0] >> (h * 32))) + bs[0];
            v.y = __uint_as_float((unsigned)(acc[p][1] >> (h * 32))) + bs[1];
            v.z = __uint_as_float((unsigned)(acc[p][2] >> (h * 32))) + bs[2];
            v.w = __uint_as_float((unsigned)(acc[p][3] >> (h * 32))) + bs[3];
            if (Add) {
                float4 ad = *(const float4*)(Add + rowoff(1, m, addi, H_) + n0 + tx * 4);
                v.x += ad.x; v.y += ad.y; v.z += ad.z; v.w += ad.w;
            }
            *(float4*)(C + rowoff(cMode, m, ci, ldc) + n0 + tx * 4) = v;
        }
    }
}

// ============================================================================
// NN GEMM for matrix powers: C = A @ B, 512x512x512 row-major.
// Grid 128 (16mt x 8nt), tile 32m x 64n, K-tile 16, 256 threads, 2x4 micro.
// ============================================================================
__global__ __launch_bounds__(256) void gemm_nn_pow(
    const float* __restrict__ A, const float* __restrict__ Bm, float* __restrict__ C)
{
    __shared__ float As[16 * 36];
    __shared__ float Bs[16 * 68];
    const int tid = threadIdx.x;
    const int mt = blockIdx.x >> 3, nt = blockIdx.x & 7;
    const int ty = tid >> 4, tx = tid & 15;
    float acc[2][4] = {};
    for (int k0 = 0; k0 < H_; k0 += 16) {
        __syncthreads();
        if (tid < 128) {
            int m = tid >> 2, k4 = (tid & 3) * 4;
            float4 a = *(const float4*)(A + (size_t)(mt * 32 + m) * H_ + k0 + k4);
            As[(k4 + 0) * 36 + m] = a.x; As[(k4 + 1) * 36 + m] = a.y;
            As[(k4 + 2) * 36 + m] = a.z; As[(k4 + 3) * 36 + m] = a.w;
        }
        {
            int k = tid >> 4, j4 = (tid & 15) * 4;
            float4 b = *(const float4*)(Bm + (size_t)(k0 + k) * H_ + nt * 64 + j4);
            *(float4*)(Bs + k * 68 + j4) = b;
        }
        __syncthreads();
#pragma unroll
        for (int kk = 0; kk < 16; kk++) {
            float a0 = As[kk * 36 + ty * 2];
            float a1 = As[kk * 36 + ty * 2 + 1];
            float4 b = *(const float4*)(Bs + kk * 68 + tx * 4);
            acc[0][0] = fmaf(a0, b.x, acc[0][0]); acc[0][1] = fmaf(a0, b.y, acc[0][1]);
            acc[0][2] = fmaf(a0, b.z, acc[0][2]); acc[0][3] = fmaf(a0, b.w, acc[0][3]);
            acc[1][0] = fmaf(a1, b.x, acc[1][0]); acc[1][1] = fmaf(a1, b.y, acc[1][1]);
            acc[1][2] = fmaf(a1, b.z, acc[1][2]); acc[1][3] = fmaf(a1, b.w, acc[1][3]);
        }
    }
#pragma unroll
    for (int im = 0; im < 2; im++) {
        float4 o = { acc[im][0], acc[im][1], acc[im][2], acc[im][3] };
        *(float4*)(C + (size_t)(mt * 32 + ty * 2 + im) * H_ + nt * 64 + tx * 4) = o;
    }
}

// ============================================================================
// Phase B: persistent 64-step boundary scan. Hn[t+1] = Hn[t] @ Q^T + F[t].
// 128 CTAs x 128 thr; CTA c: bg=c&3 (8 b's), jg=c>>2 (16 j's). Q in smem.
// Monotonic replay-safe grid barrier (R2-proven).
// ============================================================================
__global__ __launch_bounds__(128) void phaseB(
    const float* __restrict__ F, const float* __restrict__ Q, float* __restrict__ Hn)
{
    extern __shared__ float sm[];
    float (*Wsm)[516] = (float(*)[516])sm;
    float (*hsm)[516] = (float(*)[516])(sm + 16 * 516);
    float (*red)[132] = (float(*)[132])(sm + 24 * 516);
    const int tid = threadIdx.x, c = blockIdx.x, bg = c & 3, jg = c >> 2;

    for (int i = tid; i < 16 * 128; i += 128) {
        int row = i >> 7, c4 = (i & 127) << 2;
        *(float4*)&Wsm[row][c4] = *(const float4*)(Q + (size_t)(jg * 16 + row) * H_ + c4);
    }
    const unsigned base = g_flags[c];
    const int ks = tid >> 3, pos = tid & 7;
    const int pb = (pos & 1) * 4, pj = (pos >> 1) * 4, kc = ks * 4;

    for (int t = 0; t < NCH_; t++) {
        for (int i = tid; i < 1024; i += 128) {
            int rb = i >> 7, c4 = (i & 127) << 2;
            *(float4*)&hsm[rb][c4] =
                __ldcg((const float4*)(Hn + ((size_t)t * B_ + bg * 8 + rb) * H_ + c4));
        }
        __syncthreads();
        float acc[4][4] = {};
#pragma unroll
        for (int g = 0; g < 8; g++) {
            int col = g * 64 + kc;
            float4 h4[4], w4[4];
#pragma unroll
            for (int i = 0; i < 4; i++) h4[i] = *(const float4*)&hsm[pb + i][col];
#pragma unroll
            for (int j = 0; j < 4; j++) w4[j] = *(const float4*)&Wsm[pj + j][col];
#pragma unroll
            for (int i = 0; i < 4; i++)
#pragma unroll
                for (int j = 0; j < 4; j++) {
                    acc[i][j] = fmaf(h4[i].x, w4[j].x, acc[i][j]);
                    acc[i][j] = fmaf(h4[i].y, w4[j].y, acc[i][j]);
                    acc[i][j] = fmaf(h4[i].z, w4[j].z, acc[i][j]);
                    acc[i][j] = fmaf(h4[i].w, w4[j].w, acc[i][j]);
                }
        }
#pragma unroll
        for (int i = 0; i < 4; i++)
#pragma unroll
            for (int j = 0; j < 4; j++)
                red[ks][(pb + i) * 16 + pj + j] = acc[i][j];
        __syncthreads();
        float s = 0.f;
#pragma unroll
        for (int q = 0; q < 16; q++) s += red[q][tid];

        const int bl = tid >> 4, jl = tid & 15;
        const int b = bg * 8 + bl, j = jg * 16 + jl;
        Hn[((size_t)(t + 1) * B_ + b) * H_ + j] = s + F[((size_t)t * B_ + b) * H_ + j];

        __threadfence();
        __syncthreads();
        const unsigned tgt = base + (unsigned)t + 1u;
        if (tid == 0) g_flags[c] = tgt;
        if (c == 0 && tid < 32) {
            for (;;) {
                bool ok = true;
                for (int q = tid; q < 128; q += 32)
                    if ((int)(g_flags[q] - tgt) < 0) ok = false;
                if (__all_sync(0xffffffffu, ok)) break;
            }
            if (tid == 0) { __threadfence(); g_rel = tgt; }
        }
        if (tid == 0) { while ((int)(g_rel - tgt) < 0) {} }
        __syncthreads();
        __threadfence();
    }
}

// ============================================================================
// Row softmax over 256 cols, one warp per row, in place.
// ============================================================================
__global__ __launch_bounds__(256) void softmax_rows(float* __restrict__ C)
{
    const int row = blockIdx.x * 8 + (threadIdx.x >> 5);
    const int lane = threadIdx.x & 31;
    float* p = C + (size_t)row * O_;
    float4 v0 = *(const float4*)(p + lane * 8);
    float4 v1 = *(const float4*)(p + lane * 8 + 4);
    float mx = fmaxf(fmaxf(fmaxf(v0.x, v0.y), fmaxf(v0.z, v0.w)),
                     fmaxf(fmaxf(v1.x, v1.y), fmaxf(v1.z, v1.w)));
#pragma unroll
    for (int o = 16; o; o >>= 1) mx = fmaxf(mx, __shfl_xor_sync(0xffffffffu, mx, o));
    v0.x = __expf(v0.x - mx); v0.y = __expf(v0.y - mx);
    v0.z = __expf(v0.z - mx); v0.w = __expf(v0.w - mx);
    v1.x = __expf(v1.x - mx); v1.y = __expf(v1.y - mx);
    v1.z = __expf(v1.z - mx); v1.w = __expf(v1.w - mx);
    float s = v0.x + v0.y + v0.z + v0.w + v1.x + v1.y + v1.z + v1.w;
#pragma unroll
    for (int o = 16; o; o >>= 1) s += __shfl_xor_sync(0xffffffffu, s, o);
    const float inv = 1.0f / s;
    v0.x *= inv; v0.y *= inv; v0.z *= inv; v0.w *= inv;
    v1.x *= inv; v1.y *= inv; v1.z *= inv; v1.w *= inv;
    *(float4*)(p + lane * 8) = v0;
    *(float4*)(p + lane * 8 + 4) = v1;
}

// ============================================================================
// Orchestration. Output layout: [ out (B,T,O) | z (B,T,H) ]
// ============================================================================
extern "C" void kernel_launch(void* const* d_in, const int* in_sizes, int n_in,
                              void* d_out, int out_size)
{
    (void)in_sizes; (void)n_in; (void)out_size;
    const float* x     = (const float*)d_in[0];
    const float* h0    = (const float*)d_in[1];
    const float* W_ih  = (const float*)d_in[2];
    const float* W_hh  = (const float*)d_in[3];
    const float* b_ih  = (const float*)d_in[4];
    const float* b_hh  = (const float*)d_in[5];
    const float* W_lin = (const float*)d_in[6];
    const float* b_lin = (const float*)d_in[7];

    float* outp = (float*)d_out;
    float* zp = outp + (size_t)B_ * T_ * O_;

    float *xw, *Sa, *Sb, *Hin, *p0, *p1;
    cudaGetSymbolAddress((void**)&xw, g_xw);
    cudaGetSymbolAddress((void**)&Sa, g_Sa);
    cudaGetSymbolAddress((void**)&Sb, g_Sb);
    cudaGetSymbolAddress((void**)&Hin, g_Hinit);
    cudaGetSymbolAddress((void**)&p0, g_p0);
    cudaGetSymbolAddress((void**)&p1, g_p1);

    const int pb_smem = (24 * 516 + 16 * 132) * 4;
    cudaFuncSetAttribute(phaseB, cudaFuncAttributeMaxDynamicSharedMemorySize, pb_smem);

    // Q = W_hh^32 via 5 squarings (so (W^T)^32 = Q^T, NT-compatible)
    gemm_nn_pow<<<128, 256>>>(W_hh, W_hh, p0);
    gemm_nn_pow<<<128, 256>>>(p0, p0, p1);
    gemm_nn_pow<<<128, 256>>>(p1, p1, p0);
    gemm_nn_pow<<<128, 256>>>(p0, p0, p1);
    gemm_nn_pow<<<128, 256>>>(p1, p1, p0);

    // H_init[0] = h0
    cudaMemcpyAsync(Hin, h0, (size_t)B_ * H_ * sizeof(float),
                    cudaMemcpyDeviceToDevice, 0);

    // xw = x @ W_ih^T + (b_ih + b_hh)   [65536 x 512], K=256
    gemm_u<<<dim3(8, 512), 256>>>(x, 0, 0, D_, W_ih, D_,
                                  xw, 0, 0, H_, nullptr, 0, b_ih, b_hh);

    // Phase A: chunks from zero init; S_i = S_{i-1} @ W^T + xw_i. F -> g_Sa.
    gemm_u<<<dim3(8, 16), 256>>>(xw, 1, 0, H_, W_hh, H_,
                                 Sa, 0, 0, H_, xw, 1, nullptr, nullptr);
    for (int i = 2; i < CH_; i++) {
        const float* src = (i & 1) ? Sb : Sa;
        float* dst = (i & 1) ? Sa : Sb;
        gemm_u<<<dim3(8, 16), 256>>>(src, 0, 0, H_, W_hh, H_,
                                     dst, 0, 0, H_, xw, i, nullptr, nullptr);
    }

    // Phase B: 64 sequential boundary combines
    phaseB<<<128, 128, pb_smem>>>(Sa, p0, Hin);

    // Phase C: re-run chunks from true boundary states, write z
    gemm_u<<<dim3(8, 16), 256>>>(Hin, 0, 0, H_, W_hh, H_,
                                 zp, 1, 0, H_, xw, 0, nullptr, nullptr);
    for (int i = 1; i < CH_; i++)
        gemm_u<<<dim3(8, 16), 256>>>(zp, 1, i - 1, H_, W_hh, H_,
                                     zp, 1, i, H_, xw, i, nullptr, nullptr);

    // logits = z @ W_lin^T + b_lin   [65536 x 256], K=512
    gemm_u<<<dim3(4, 512), 256>>>(zp, 0, 0, H_, W_lin, H_,
                                  outp, 0, 0, O_, nullptr, 0, b_lin, nullptr);

    softmax_rows<<<BT_ / 8, 256>>>(outp);
}

// round 14
// speedup vs baseline: 1.0258x; 1.0190x over previous
#include <cuda_runtime.h>
#include <cstdint>
typedef unsigned long long ull;

#define B_ 32
#define T_ 2048
#define D_ 256
#define H_ 512
#define O_ 256
#define BT_ 65536
#define CH_ 32
#define NCH_ 64

__device__ __align__(16) float g_xw[(size_t)BT_ * H_];
__device__ __align__(16) float g_Sa[NCH_ * B_ * H_];
__device__ __align__(16) float g_Sb[NCH_ * B_ * H_];
__device__ __align__(16) float g_Hinit[(NCH_ + 1) * B_ * H_];
__device__ __align__(16) float g_p0[H_ * H_];
__device__ __align__(16) float g_p1[H_ * H_];
__device__ volatile unsigned g_flags[128];
__device__ volatile unsigned g_rel;

#define FMA2(d,a,b) asm("fma.rn.f32x2 %0, %1, %2, %0;" : "+l"(d) : "l"(a), "l"(b))
#define PACK2(o,x) { unsigned u_ = __float_as_uint(x); \
    asm("mov.b64 %0,{%1,%1};" : "=l"(o) : "r"(u_)); }

// mode 0: linear rows (r*ld). mode 1: (b,t)-mapped rows of a [B][T][H] tensor,
// r -> b = r&31, chunk = r>>5, t = chunk*CH_ + i.
__device__ __forceinline__ size_t rowoff(int mode, long r, int i, int ld) {
    if (mode == 0) return (size_t)r * ld;
    return ((size_t)(r & 31) * T_ + (size_t)(r >> 5) * CH_ + i) * H_;
}

// ============================================================================
// Unified NT GEMM, tile 128(M)x64(N)x16(K), 256 threads, micro 8mx4n, FFMA2.
// C[m][n] = sum_k A[m][k]*Bm[n][k] (+ Add[m][n]) (+ bias1[n] (+ bias2[n]))
// ============================================================================
__global__ __launch_bounds__(256) void gemm_u(
    const float* __restrict__ A, int aMode, int ai, int lda,
    const float* __restrict__ Bm, int K,
    float* __restrict__ C, int cMode, int ci, int ldc,
    const float* __restrict__ Add, int addi,
    const float* __restrict__ bias1, const float* __restrict__ bias2)
{
    __shared__ float As[16][132];
    __shared__ float Bs[16][68];
    const int tid = threadIdx.x;
    const long m0 = (long)blockIdx.y * 128;
    const int n0 = blockIdx.x * 64;
    const int ty = tid >> 4, tx = tid & 15;
    const int ar = tid >> 1, ak = (tid & 1) * 8;
    const int br = tid >> 2, bk = (tid & 3) * 4;
    const float* Ap = A + rowoff(aMode, m0 + ar, ai, lda) + ak;
    const float* Bp = Bm + (size_t)(n0 + br) * K + bk;

    ull acc[4][4] = {};
    for (int k0 = 0; k0 < K; k0 += 16) {
        float4 a0 = *(const float4*)(Ap + k0);
        float4 a1 = *(const float4*)(Ap + k0 + 4);
        float4 bv = *(const float4*)(Bp + k0);
        __syncthreads();
        As[ak + 0][ar] = a0.x; As[ak + 1][ar] = a0.y;
        As[ak + 2][ar] = a0.z; As[ak + 3][ar] = a0.w;
        As[ak + 4][ar] = a1.x; As[ak + 5][ar] = a1.y;
        As[ak + 6][ar] = a1.z; As[ak + 7][ar] = a1.w;
        Bs[bk + 0][br] = bv.x; Bs[bk + 1][br] = bv.y;
        Bs[bk + 2][br] = bv.z; Bs[bk + 3][br] = bv.w;
        __syncthreads();
#pragma unroll
        for (int k = 0; k < 16; k++) {
            const ull* ap = (const ull*)&As[k][ty * 8];
            ull a2[4] = { ap[0], ap[1], ap[2], ap[3] };
            float4 b = *(const float4*)&Bs[k][tx * 4];
            ull b2[4];
            PACK2(b2[0], b.x); PACK2(b2[1], b.y);
            PACK2(b2[2], b.z); PACK2(b2[3], b.w);
#pragma unroll
            for (int p = 0; p < 4; p++)
#pragma unroll
                for (int j = 0; j < 4; j++) FMA2(acc[p][j], a2[p], b2[j]);
        }
    }

    float bs[4] = {0.f, 0.f, 0.f, 0.f};
    if (bias1) {
#pragma unroll
        for (int j = 0; j < 4; j++) bs[j] = bias1[n0 + tx * 4 + j];
    }
    if (bias2) {
#pragma unroll
        for (int j = 0; j < 4; j++) bs[j] += bias2[n0 + tx * 4 + j];
    }
#pragma unroll
    for (int p = 0; p < 4; p++) {
#pragma unroll
        for (int h = 0; h < 2; h++) {
            long m = m0 + ty * 8 + p * 2 + h;
            float4 v;
            v.x = __uint_as_float((unsigned)(acc[p][0] >> (h * 32))) + bs[0];
            v.y = __uint_as_float((unsigned)(acc[p][1] >> (h * 32))) + bs[1];
            v.z = __uint_as_float((unsigned)(acc[p][2] >> (h * 32))) + bs[2];
            v.w = __uint_as_float((unsigned)(acc[p][3] >> (h * 32))) + bs[3];
            if (Add) {
                float4 ad = *(const float4*)(Add + rowoff(1, m, addi, H_) + n0 + tx * 4);
                v.x += ad.x; v.y += ad.y; v.z += ad.z; v.w += ad.w;
            }
            *(float4*)(C + rowoff(cMode, m, ci, ldc) + n0 + tx * 4) = v;
        }
    }
}

// ============================================================================
// NN GEMM for matrix powers: C = A @ B, 512x512x512 row-major.
// Grid 128 (16mt x 8nt), tile 32m x 64n, K-tile 16, 256 threads, 2x4 micro.
// ============================================================================
__global__ __launch_bounds__(256) void gemm_nn_pow(
    const float* __restrict__ A, const float* __restrict__ Bm, float* __restrict__ C)
{
    __shared__ float As[16 * 36];
    __shared__ float Bs[16 * 68];
    const int tid = threadIdx.x;
    const int mt = blockIdx.x >> 3, nt = blockIdx.x & 7;
    const int ty = tid >> 4, tx = tid & 15;
    float acc[2][4] = {};
    for (int k0 = 0; k0 < H_; k0 += 16) {
        __syncthreads();
        if (tid < 128) {
            int m = tid >> 2, k4 = (tid & 3) * 4;
            float4 a = *(const float4*)(A + (size_t)(mt * 32 + m) * H_ + k0 + k4);
            As[(k4 + 0) * 36 + m] = a.x; As[(k4 + 1) * 36 + m] = a.y;
            As[(k4 + 2) * 36 + m] = a.z; As[(k4 + 3) * 36 + m] = a.w;
        }
        {
            int k = tid >> 4, j4 = (tid & 15) * 4;
            float4 b = *(const float4*)(Bm + (size_t)(k0 + k) * H_ + nt * 64 + j4);
            *(float4*)(Bs + k * 68 + j4) = b;
        }
        __syncthreads();
#pragma unroll
        for (int kk = 0; kk < 16; kk++) {
            float a0 = As[kk * 36 + ty * 2];
            float a1 = As[kk * 36 + ty * 2 + 1];
            float4 b = *(const float4*)(Bs + kk * 68 + tx * 4);
            acc[0][0] = fmaf(a0, b.x, acc[0][0]); acc[0][1] = fmaf(a0, b.y, acc[0][1]);
            acc[0][2] = fmaf(a0, b.z, acc[0][2]); acc[0][3] = fmaf(a0, b.w, acc[0][3]);
            acc[1][0] = fmaf(a1, b.x, acc[1][0]); acc[1][1] = fmaf(a1, b.y, acc[1][1]);
            acc[1][2] = fmaf(a1, b.z, acc[1][2]); acc[1][3] = fmaf(a1, b.w, acc[1][3]);
        }
    }
#pragma unroll
    for (int im = 0; im < 2; im++) {
        float4 o = { acc[im][0], acc[im][1], acc[im][2], acc[im][3] };
        *(float4*)(C + (size_t)(mt * 32 + ty * 2 + im) * H_ + nt * 64 + tx * 4) = o;
    }
}

// ============================================================================
// Phase B: persistent 64-step boundary scan. Hn[t+1] = Hn[t] @ Q^T + F[t].
// 128 CTAs x 128 thr; CTA c: bg=c&3 (8 b's), jg=c>>2 (16 j's). Q in smem.
// Monotonic replay-safe grid barrier (R2-proven).
// ============================================================================
__global__ __launch_bounds__(128) void phaseB(
    const float* __restrict__ F, const float* __restrict__ Q, float* __restrict__ Hn)
{
    extern __shared__ float sm[];
    float (*Wsm)[516] = (float(*)[516])sm;
    float (*hsm)[516] = (float(*)[516])(sm + 16 * 516);
    float (*red)[132] = (float(*)[132])(sm + 24 * 516);
    const int tid = threadIdx.x, c = blockIdx.x, bg = c & 3, jg = c >> 2;

    for (int i = tid; i < 16 * 128; i += 128) {
        int row = i >> 7, c4 = (i & 127) << 2;
        *(float4*)&Wsm[row][c4] = *(const float4*)(Q + (size_t)(jg * 16 + row) * H_ + c4);
    }
    const unsigned base = g_flags[c];
    const int ks = tid >> 3, pos = tid & 7;
    const int pb = (pos & 1) * 4, pj = (pos >> 1) * 4, kc = ks * 4;

    for (int t = 0; t < NCH_; t++) {
        for (int i = tid; i < 1024; i += 128) {
            int rb = i >> 7, c4 = (i & 127) << 2;
            *(float4*)&hsm[rb][c4] =
                __ldcg((const float4*)(Hn + ((size_t)t * B_ + bg * 8 + rb) * H_ + c4));
        }
        __syncthreads();
        float acc[4][4] = {};
#pragma unroll
        for (int g = 0; g < 8; g++) {
            int col = g * 64 + kc;
            float4 h4[4], w4[4];
#pragma unroll
            for (int i = 0; i < 4; i++) h4[i] = *(const float4*)&hsm[pb + i][col];
#pragma unroll
            for (int j = 0; j < 4; j++) w4[j] = *(const float4*)&Wsm[pj + j][col];
#pragma unroll
            for (int i = 0; i < 4; i++)
#pragma unroll
                for (int j = 0; j < 4; j++) {
                    acc[i][j] = fmaf(h4[i].x, w4[j].x, acc[i][j]);
                    acc[i][j] = fmaf(h4[i].y, w4[j].y, acc[i][j]);
                    acc[i][j] = fmaf(h4[i].z, w4[j].z, acc[i][j]);
                    acc[i][j] = fmaf(h4[i].w, w4[j].w, acc[i][j]);
                }
        }
#pragma unroll
        for (int i = 0; i < 4; i++)
#pragma unroll
            for (int j = 0; j < 4; j++)
                red[ks][(pb + i) * 16 + pj + j] = acc[i][j];
        __syncthreads();
        float s = 0.f;
#pragma unroll
        for (int q = 0; q < 16; q++) s += red[q][tid];

        const int bl = tid >> 4, jl = tid & 15;
        const int b = bg * 8 + bl, j = jg * 16 + jl;
        Hn[((size_t)(t + 1) * B_ + b) * H_ + j] = s + F[((size_t)t * B_ + b) * H_ + j];

        __threadfence();
        __syncthreads();
        const unsigned tgt = base + (unsigned)t + 1u;
        if (tid == 0) g_flags[c] = tgt;
        if (c == 0 && tid < 32) {
            for (;;) {
                bool ok = true;
                for (int q = tid; q < 128; q += 32)
                    if ((int)(g_flags[q] - tgt) < 0) ok = false;
                if (__all_sync(0xffffffffu, ok)) break;
            }
            if (tid == 0) { __threadfence(); g_rel = tgt; }
        }
        if (tid == 0) { while ((int)(g_rel - tgt) < 0) {} }
        __syncthreads();
        __threadfence();
    }
}

// ============================================================================
// Row softmax over 256 cols, one warp per row, in place.
// ============================================================================
__global__ __launch_bounds__(256) void softmax_rows(float* __restrict__ C)
{
    const int row = blockIdx.x * 8 + (threadIdx.x >> 5);
    const int lane = threadIdx.x & 31;
    float* p = C + (size_t)row * O_;
    float4 v0 = *(const float4*)(p + lane * 8);
    float4 v1 = *(const float4*)(p + lane * 8 + 4);
    float mx = fmaxf(fmaxf(fmaxf(v0.x, v0.y), fmaxf(v0.z, v0.w)),
                     fmaxf(fmaxf(v1.x, v1.y), fmaxf(v1.z, v1.w)));
#pragma unroll
    for (int o = 16; o; o >>= 1) mx = fmaxf(mx, __shfl_xor_sync(0xffffffffu, mx, o));
    v0.x = __expf(v0.x - mx); v0.y = __expf(v0.y - mx);
    v0.z = __expf(v0.z - mx); v0.w = __expf(v0.w - mx);
    v1.x = __expf(v1.x - mx); v1.y = __expf(v1.y - mx);
    v1.z = __expf(v1.z - mx); v1.w = __expf(v1.w - mx);
    float s = v0.x + v0.y + v0.z + v0.w + v1.x + v1.y + v1.z + v1.w;
#pragma unroll
    for (int o = 16; o; o >>= 1) s += __shfl_xor_sync(0xffffffffu, s, o);
    const float inv = 1.0f / s;
    v0.x *= inv; v0.y *= inv; v0.z *= inv; v0.w *= inv;
    v1.x *= inv; v1.y *= inv; v1.z *= inv; v1.w *= inv;
    *(float4*)(p + lane * 8) = v0;
    *(float4*)(p + lane * 8 + 4) = v1;
}

// ============================================================================
// Orchestration. Output layout: [ out (B,T,O) | z (B,T,H) ]
// ============================================================================
extern "C" void kernel_launch(void* const* d_in, const int* in_sizes, int n_in,
                              void* d_out, int out_size)
{
    (void)in_sizes; (void)n_in; (void)out_size;
    const float* x     = (const float*)d_in[0];
    const float* h0    = (const float*)d_in[1];
    const float* W_ih  = (const float*)d_in[2];
    const float* W_hh  = (const float*)d_in[3];
    const float* b_ih  = (const float*)d_in[4];
    const float* b_hh  = (const float*)d_in[5];
    const float* W_lin = (const float*)d_in[6];
    const float* b_lin = (const float*)d_in[7];

    float* outp = (float*)d_out;
    float* zp = outp + (size_t)B_ * T_ * O_;

    float *xw, *Sa, *Sb, *Hin, *p0, *p1;
    cudaGetSymbolAddress((void**)&xw, g_xw);
    cudaGetSymbolAddress((void**)&Sa, g_Sa);
    cudaGetSymbolAddress((void**)&Sb, g_Sb);
    cudaGetSymbolAddress((void**)&Hin, g_Hinit);
    cudaGetSymbolAddress((void**)&p0, g_p0);
    cudaGetSymbolAddress((void**)&p1, g_p1);

    const int pb_smem = (24 * 516 + 16 * 132) * 4;
    cudaFuncSetAttribute(phaseB, cudaFuncAttributeMaxDynamicSharedMemorySize, pb_smem);

    // Q = W_hh^32 via 5 squarings (so (W^T)^32 = Q^T, NT-compatible)
    gemm_nn_pow<<<128, 256>>>(W_hh, W_hh, p0);
    gemm_nn_pow<<<128, 256>>>(p0, p0, p1);
    gemm_nn_pow<<<128, 256>>>(p1, p1, p0);
    gemm_nn_pow<<<128, 256>>>(p0, p0, p1);
    gemm_nn_pow<<<128, 256>>>(p1, p1, p0);

    // H_init[0] = h0
    cudaMemcpyAsync(Hin, h0, (size_t)B_ * H_ * sizeof(float),
                    cudaMemcpyDeviceToDevice, 0);

    // xw = x @ W_ih^T + (b_ih + b_hh)   [65536 x 512], K=256
    gemm_u<<<dim3(8, 512), 256>>>(x, 0, 0, D_, W_ih, D_,
                                  xw, 0, 0, H_, nullptr, 0, b_ih, b_hh);

    // Phase A: chunks from zero init; S_i = S_{i-1} @ W^T + xw_i. F -> g_Sa.
    gemm_u<<<dim3(8, 16), 256>>>(xw, 1, 0, H_, W_hh, H_,
                                 Sa, 0, 0, H_, xw, 1, nullptr, nullptr);
    for (int i = 2; i < CH_; i++) {
        const float* src = (i & 1) ? Sb : Sa;
        float* dst = (i & 1) ? Sa : Sb;
        gemm_u<<<dim3(8, 16), 256>>>(src, 0, 0, H_, W_hh, H_,
                                     dst, 0, 0, H_, xw, i, nullptr, nullptr);
    }

    // Phase B: 64 sequential boundary combines
    phaseB<<<128, 128, pb_smem>>>(Sa, p0, Hin);

    // Phase C: re-run chunks from true boundary states, write z
    gemm_u<<<dim3(8, 16), 256>>>(Hin, 0, 0, H_, W_hh, H_,
                                 zp, 1, 0, H_, xw, 0, nullptr, nullptr);
    for (int i = 1; i < CH_; i++)
        gemm_u<<<dim3(8, 16), 256>>>(zp, 1, i - 1, H_, W_hh, H_,
                                     zp, 1, i, H_, xw, i, nullptr, nullptr);

    // logits = z @ W_lin^T + b_lin   [65536 x 256], K=512
    gemm_u<<<dim3(4, 512), 256>>>(zp, 0, 0, H_, W_lin, H_,
                                  outp, 0, 0, O_, nullptr, 0, b_lin, nullptr);

    softmax_rows<<<BT_ / 8, 256>>>(outp);
}